// round 8
// baseline (speedup 1.0000x reference)
#include <cuda_runtime.h>
#include <mma.h>
#include <math.h>
#include <stdint.h>

using namespace nvcuda;

#define DD 256
#define TWO_D 512
#define NB 16
#define AL 1024
#define TL 512

// ---------------- scratch (no allocations allowed) ----------------
__device__ float g_art0[NB * AL * DD];
__device__ float g_art1[NB * AL * DD];
__device__ float g_tpl0[NB * TL * DD];
__device__ float g_tpl1[NB * TL * DD];
__device__ float g_a2[NB * AL];
__device__ float g_t2[NB * TL];
__device__ float g_rowmax[NB * AL];

__device__ __forceinline__ float tf32_hi(float v) {
    return __uint_as_float(__float_as_uint(v) & 0xFFFFE000u);
}

// conv tile geometry
#define BM 128
#define BN 128
#define BK 16
#define A_STR 24
#define B_STR 136
#define C_STR 132
#define SZ_A (BM * A_STR)            // floats per A stage
#define SZ_B (BK * B_STR)            // floats per B stage
#define CONV_SMEM ((4 * SZ_A + 4 * SZ_B) * 4)   // bytes (83968)

// ---------------- embedding gather ----------------
__global__ void gather_kernel(const int* __restrict__ idx,
                              const float* __restrict__ emb,
                              float* __restrict__ out, int nrows)
{
    int t = blockIdx.x * blockDim.x + threadIdx.x;
    int total = nrows * (DD / 4);
    if (t >= total) return;
    int row = t / (DD / 4);
    int c4  = t % (DD / 4);
    int w = idx[row];
    reinterpret_cast<float4*>(out)[(size_t)row * (DD / 4) + c4] =
        reinterpret_cast<const float4*>(emb)[(size_t)w * (DD / 4) + c4];
}

// ---------------- wmma tf32 conv1d(K=3, dilated) + GLU + residual ----------------
// CTA: 128 positions x 128 cols (n<64 -> a-col co0+n ; n>=64 -> g-col co0+192+n).
// 3xtf32 (hi/lo split, both tf32-masked) => fp32-grade accuracy on tensor pipe.
__global__ __launch_bounds__(256) void conv_tc_kernel(
    const float* __restrict__ x, float* __restrict__ out,
    const float* __restrict__ w, const float* __restrict__ bias,
    int L, int dil)
{
    extern __shared__ float sm[];
    float* sAh = sm;                         // [2][BM][A_STR]
    float* sAl = sm + 2 * SZ_A;
    float* sBh = sm + 4 * SZ_A;              // [2][BK][B_STR]
    float* sBl = sm + 4 * SZ_A + 2 * SZ_B;
    float* sC  = sm;                         // [BM][C_STR]  (union, used after loop)

    const int tid = threadIdx.x;
    const int wid = tid >> 5;
    const int l0  = blockIdx.x * BM;
    const int co0 = blockIdx.y * 64;
    const int b   = blockIdx.z;
    const float* xb = x + (size_t)b * L * DD;

    // A staging map: row ar (0..127), cols ac..ac+7
    const int ar = tid >> 1;
    const int ac = (tid & 1) * 8;
    // B staging map: col bc (0..127), rows bk0..bk0+7
    const int bc  = tid & 127;
    const int bk0 = (tid >> 7) * 8;
    const int coln = (bc < 64) ? (co0 + bc) : (co0 + 192 + bc);

    float pa[8], pb[8];

    wmma::fragment<wmma::accumulator, 16, 16, 8, float> acc[2][4];
#pragma unroll
    for (int mi = 0; mi < 2; mi++)
#pragma unroll
        for (int ni = 0; ni < 4; ni++)
            wmma::fill_fragment(acc[mi][ni], 0.f);

    const int wm = (wid & 3) * 32;   // warp row base
    const int wn = (wid >> 2) * 64;  // warp col base

    // ---- fetch chunk 0 ----
    {
        const int p = l0 + ar - dil;   // tap 0
        if (p >= 0 && p < L) {
            float4 v0 = *reinterpret_cast<const float4*>(&xb[(size_t)p * DD + ac]);
            float4 v1 = *reinterpret_cast<const float4*>(&xb[(size_t)p * DD + ac + 4]);
            pa[0]=v0.x; pa[1]=v0.y; pa[2]=v0.z; pa[3]=v0.w;
            pa[4]=v1.x; pa[5]=v1.y; pa[6]=v1.z; pa[7]=v1.w;
        } else {
#pragma unroll
            for (int i = 0; i < 8; i++) pa[i] = 0.f;
        }
        const float* wr = w + (size_t)bk0 * TWO_D + coln;
#pragma unroll
        for (int i = 0; i < 8; i++) pb[i] = wr[(size_t)i * TWO_D];
    }
    // ---- stage chunk 0 ----
    {
        float* ah = sAh + ar * A_STR + ac;
        float* al = sAl + ar * A_STR + ac;
#pragma unroll
        for (int i = 0; i < 8; i++) {
            float h = tf32_hi(pa[i]);
            ah[i] = h;
            al[i] = tf32_hi(pa[i] - h);
        }
        float* bh = sBh + bk0 * B_STR + bc;
        float* bl = sBl + bk0 * B_STR + bc;
#pragma unroll
        for (int i = 0; i < 8; i++) {
            float h = tf32_hi(pb[i]);
            bh[i * B_STR] = h;
            bl[i * B_STR] = tf32_hi(pb[i] - h);
        }
    }
    __syncthreads();

    for (int c = 0; c < 48; ++c) {
        const int st = c & 1;

        // prefetch chunk c+1
        if (c < 47) {
            const int cn  = c + 1;
            const int tap = cn >> 4;
            const int ci0 = (cn & 15) * 16;
            const int p = l0 + ar + (tap - 1) * dil;
            if (p >= 0 && p < L) {
                float4 v0 = *reinterpret_cast<const float4*>(&xb[(size_t)p * DD + ci0 + ac]);
                float4 v1 = *reinterpret_cast<const float4*>(&xb[(size_t)p * DD + ci0 + ac + 4]);
                pa[0]=v0.x; pa[1]=v0.y; pa[2]=v0.z; pa[3]=v0.w;
                pa[4]=v1.x; pa[5]=v1.y; pa[6]=v1.z; pa[7]=v1.w;
            } else {
#pragma unroll
                for (int i = 0; i < 8; i++) pa[i] = 0.f;
            }
            const int k0 = tap * 256 + ci0;
            const float* wr = w + (size_t)(k0 + bk0) * TWO_D + coln;
#pragma unroll
            for (int i = 0; i < 8; i++) pb[i] = wr[(size_t)i * TWO_D];
        }

        // compute current chunk: 2 k8-steps
        const float* aBh = sAh + st * SZ_A;
        const float* aBl = sAl + st * SZ_A;
        const float* bBh = sBh + st * SZ_B;
        const float* bBl = sBl + st * SZ_B;
#pragma unroll
        for (int ks = 0; ks < 2; ++ks) {
            wmma::fragment<wmma::matrix_a, 16, 16, 8, wmma::precision::tf32, wmma::row_major> fah[2], fal[2];
#pragma unroll
            for (int mi = 0; mi < 2; mi++) {
                wmma::load_matrix_sync(fah[mi], aBh + (wm + mi * 16) * A_STR + ks * 8, A_STR);
                wmma::load_matrix_sync(fal[mi], aBl + (wm + mi * 16) * A_STR + ks * 8, A_STR);
            }
#pragma unroll
            for (int ni = 0; ni < 4; ni++) {
                wmma::fragment<wmma::matrix_b, 16, 16, 8, wmma::precision::tf32, wmma::row_major> fbh, fbl;
                wmma::load_matrix_sync(fbh, bBh + (ks * 8) * B_STR + wn + ni * 16, B_STR);
                wmma::load_matrix_sync(fbl, bBl + (ks * 8) * B_STR + wn + ni * 16, B_STR);
#pragma unroll
                for (int mi = 0; mi < 2; mi++) {
                    wmma::mma_sync(acc[mi][ni], fah[mi], fbh, acc[mi][ni]);
                    wmma::mma_sync(acc[mi][ni], fah[mi], fbl, acc[mi][ni]);
                    wmma::mma_sync(acc[mi][ni], fal[mi], fbh, acc[mi][ni]);
                }
            }
        }

        // stage chunk c+1 into the other buffer (safe: other warps read st only)
        if (c < 47) {
            const int sn = st ^ 1;
            float* ah = sAh + sn * SZ_A + ar * A_STR + ac;
            float* al = sAl + sn * SZ_A + ar * A_STR + ac;
#pragma unroll
            for (int i = 0; i < 8; i++) {
                float h = tf32_hi(pa[i]);
                ah[i] = h;
                al[i] = tf32_hi(pa[i] - h);
            }
            float* bh = sBh + sn * SZ_B + bk0 * B_STR + bc;
            float* bl = sBl + sn * SZ_B + bk0 * B_STR + bc;
#pragma unroll
            for (int i = 0; i < 8; i++) {
                float h = tf32_hi(pb[i]);
                bh[i * B_STR] = h;
                bl[i * B_STR] = tf32_hi(pb[i] - h);
            }
        }
        __syncthreads();
    }

    // ---- write accumulators to smem (staging buffers are dead now) ----
#pragma unroll
    for (int mi = 0; mi < 2; mi++)
#pragma unroll
        for (int ni = 0; ni < 4; ni++)
            wmma::store_matrix_sync(sC + (wm + mi * 16) * C_STR + wn + ni * 16,
                                    acc[mi][ni], C_STR, wmma::mem_row_major);
    __syncthreads();

    // ---- GLU epilogue: o = x + (a + ba) * sigmoid(g + bg) ----
    {
        const int r  = tid >> 1;
        const int j0 = (tid & 1) * 32;
        const int l  = l0 + r;
        const float* xrow = xb + (size_t)l * DD + co0;
        float* orow = out + ((size_t)b * L + l) * DD + co0;
#pragma unroll
        for (int j = 0; j < 32; j += 4) {
            float4 xv = *reinterpret_cast<const float4*>(&xrow[j0 + j]);
            float o[4];
#pragma unroll
            for (int u = 0; u < 4; ++u) {
                int jj = j0 + j + u;
                float aa = sC[r * C_STR + jj] + bias[co0 + jj];
                float gg = sC[r * C_STR + 64 + jj] + bias[DD + co0 + jj];
                float xr = (u == 0) ? xv.x : (u == 1) ? xv.y : (u == 2) ? xv.z : xv.w;
                o[u] = xr + aa * (1.f / (1.f + expf(-gg)));
            }
            *reinterpret_cast<float4*>(&orow[j0 + j]) = make_float4(o[0], o[1], o[2], o[3]);
        }
    }
}

// ---------------- row squared norms (one warp per row) ----------------
__global__ void norms_kernel(const float* __restrict__ x, float* __restrict__ out,
                             int nrows)
{
    int warp = (blockIdx.x * blockDim.x + threadIdx.x) >> 5;
    int lane = threadIdx.x & 31;
    if (warp >= nrows) return;
    const float* r = x + (size_t)warp * DD;
    float s = 0.f;
#pragma unroll
    for (int c = lane * 2; c < DD; c += 64) {
        float2 v = *reinterpret_cast<const float2*>(&r[c]);
        s += v.x * v.x + v.y * v.y;
    }
#pragma unroll
    for (int o = 16; o; o >>= 1) s += __shfl_xor_sync(0xffffffffu, s, o);
    if (lane == 0) out[warp] = s;
}

// ---------------- fused distance GEMM + exp + mask + row-max ----------------
__global__ __launch_bounds__(256) void rowmax_kernel(
    const float* __restrict__ art, const float* __restrict__ tpl,
    const float* __restrict__ a2, const float* __restrict__ t2,
    const float* __restrict__ amask, const float* __restrict__ tmask,
    float* __restrict__ rowmax)
{
    __shared__ __align__(16) float As[16][68];
    __shared__ __align__(16) float Bs[16][68];

    const int l0  = blockIdx.x * 64;
    const int b   = blockIdx.y;
    const int tid = threadIdx.x;
    const int tx  = tid & 15;
    const int ty  = tid >> 4;

    const float* ab = art + (size_t)b * AL * DD;
    const float* tb = tpl + (size_t)b * TL * DD;

    const int am  = tid >> 2;
    const int akk = (tid & 3) * 4;

    float rmax[4] = {0.f, 0.f, 0.f, 0.f};

    for (int t0 = 0; t0 < TL; t0 += 64) {
        float acc[4][4];
#pragma unroll
        for (int i = 0; i < 4; i++)
#pragma unroll
            for (int j = 0; j < 4; j++) acc[i][j] = 0.f;

        for (int c = 0; c < 16; ++c) {
            int d0 = c * 16;
            float4 va = *reinterpret_cast<const float4*>(&ab[(size_t)(l0 + am) * DD + d0 + akk]);
            float4 vb = *reinterpret_cast<const float4*>(&tb[(size_t)(t0 + am) * DD + d0 + akk]);
            __syncthreads();
            As[akk + 0][am] = va.x; As[akk + 1][am] = va.y;
            As[akk + 2][am] = va.z; As[akk + 3][am] = va.w;
            Bs[akk + 0][am] = vb.x; Bs[akk + 1][am] = vb.y;
            Bs[akk + 2][am] = vb.z; Bs[akk + 3][am] = vb.w;
            __syncthreads();
#pragma unroll
            for (int kk = 0; kk < 16; ++kk) {
                float4 a4 = *reinterpret_cast<const float4*>(&As[kk][ty * 4]);
                float4 b4 = *reinterpret_cast<const float4*>(&Bs[kk][tx * 4]);
                float av[4] = {a4.x, a4.y, a4.z, a4.w};
                float bv[4] = {b4.x, b4.y, b4.z, b4.w};
#pragma unroll
                for (int i = 0; i < 4; i++)
#pragma unroll
                    for (int j = 0; j < 4; j++)
                        acc[i][j] = fmaf(av[i], bv[j], acc[i][j]);
            }
        }

#pragma unroll
        for (int i = 0; i < 4; i++) {
            int l = l0 + ty * 4 + i;
            float av2 = a2[b * AL + l];
#pragma unroll
            for (int j = 0; j < 4; j++) {
                int t = t0 + tx * 4 + j;
                float dist = av2 + t2[b * TL + t] - 2.f * acc[i][j];
                dist = fmaxf(dist, 0.f);
                float s = expf(-dist) * tmask[b * TL + t];
                rmax[i] = fmaxf(rmax[i], s);
            }
        }
    }

#pragma unroll
    for (int i = 0; i < 4; i++) {
        float v = rmax[i];
#pragma unroll
        for (int o = 8; o; o >>= 1) v = fmaxf(v, __shfl_xor_sync(0xffffffffu, v, o));
        if (tx == 0) {
            int l = l0 + ty * 4 + i;
            rowmax[b * AL + l] = v * amask[b * AL + l];
        }
    }
}

// ---------------- top-10 (sorted desc) + 2-layer MLP ----------------
__global__ void final_kernel(const float* __restrict__ rowmax,
                             const float* __restrict__ ff1w, const float* __restrict__ ff1b,
                             const float* __restrict__ ff2w, const float* __restrict__ ff2b,
                             float* __restrict__ out)
{
    __shared__ float vals[AL];
    __shared__ float rv[256];
    __shared__ int   ri[256];
    __shared__ float topv[10];

    int b = blockIdx.x;
    int tid = threadIdx.x;
    for (int i = tid; i < AL; i += 256) vals[i] = rowmax[b * AL + i];
    __syncthreads();

    for (int it = 0; it < 10; ++it) {
        float bv = -1.f; int bi = 0;
        for (int i = tid; i < AL; i += 256) {
            float v = vals[i];
            if (v > bv) { bv = v; bi = i; }
        }
        rv[tid] = bv; ri[tid] = bi;
        __syncthreads();
        for (int s = 128; s; s >>= 1) {
            if (tid < s && rv[tid + s] > rv[tid]) { rv[tid] = rv[tid + s]; ri[tid] = ri[tid + s]; }
            __syncthreads();
        }
        if (tid == 0) { topv[it] = rv[0]; vals[ri[0]] = -2.f; }
        __syncthreads();
    }

    if (tid == 0) {
        float o = ff2b[0];
#pragma unroll
        for (int j = 0; j < 10; j++) {
            float h = ff1b[j];
#pragma unroll
            for (int i = 0; i < 10; i++) h += topv[i] * ff1w[i * 10 + j];
            h = fmaxf(h, 0.f);
            o += h * ff2w[j];
        }
        out[b] = o;
    }
}

// ---------------- launcher ----------------
extern "C" void kernel_launch(void* const* d_in, const int* in_sizes, int n_in,
                              void* d_out, int out_size)
{
    const int*   art_w = (const int*)d_in[0];
    const int*   tpl_w = (const int*)d_in[2];
    const float* amask = (const float*)d_in[4];
    const float* tmask = (const float*)d_in[5];
    const float* emb   = (const float*)d_in[6];
    const float* exp_w = (const float*)d_in[7];
    const float* exp_b = (const float*)d_in[8];
    const float* ref_w = (const float*)d_in[9];
    const float* ref_b = (const float*)d_in[10];
    const float* ff1w  = (const float*)d_in[11];
    const float* ff1b  = (const float*)d_in[12];
    const float* ff2w  = (const float*)d_in[13];
    const float* ff2b  = (const float*)d_in[14];
    float* out = (float*)d_out;

    float *art0, *art1, *tpl0, *tpl1, *a2, *t2, *rmax;
    cudaGetSymbolAddress((void**)&art0, g_art0);
    cudaGetSymbolAddress((void**)&art1, g_art1);
    cudaGetSymbolAddress((void**)&tpl0, g_tpl0);
    cudaGetSymbolAddress((void**)&tpl1, g_tpl1);
    cudaGetSymbolAddress((void**)&a2,   g_a2);
    cudaGetSymbolAddress((void**)&t2,   g_t2);
    cudaGetSymbolAddress((void**)&rmax, g_rowmax);

    cudaFuncSetAttribute(conv_tc_kernel,
                         cudaFuncAttributeMaxDynamicSharedMemorySize, CONV_SMEM);

    // 1. embedding gathers
    {
        int total_a = NB * AL * (DD / 4);
        gather_kernel<<<(total_a + 255) / 256, 256>>>(art_w, emb, art0, NB * AL);
        int total_t = NB * TL * (DD / 4);
        gather_kernel<<<(total_t + 255) / 256, 256>>>(tpl_w, emb, tpl0, NB * TL);
    }

    // 2. 10 residual conv-GLU blocks (wmma tf32 x3)
    const int dils[10] = {1, 2, 4, 8, 16, 32, 32, 1, 1, 1};
    for (int i = 0; i < 10; ++i) {
        const float* w  = (i < 7) ? exp_w + (size_t)i * 3 * DD * TWO_D
                                  : ref_w + (size_t)(i - 7) * 3 * DD * TWO_D;
        const float* bb = (i < 7) ? exp_b + i * TWO_D
                                  : ref_b + (i - 7) * TWO_D;
        float* ain  = (i & 1) ? art1 : art0;
        float* aout = (i & 1) ? art0 : art1;
        float* tin  = (i & 1) ? tpl1 : tpl0;
        float* tout = (i & 1) ? tpl0 : tpl1;
        conv_tc_kernel<<<dim3(AL / 128, 4, NB), 256, CONV_SMEM>>>(ain, aout, w, bb, AL, dils[i]);
        conv_tc_kernel<<<dim3(TL / 128, 4, NB), 256, CONV_SMEM>>>(tin, tout, w, bb, TL, dils[i]);
    }

    // 3. squared norms
    norms_kernel<<<(NB * AL) / 8, 256>>>(art0, a2, NB * AL);
    norms_kernel<<<(NB * TL) / 8, 256>>>(tpl0, t2, NB * TL);

    // 4. fused distance + exp + mask + row-max
    rowmax_kernel<<<dim3(AL / 64, NB), 256>>>(art0, tpl0, a2, t2, amask, tmask, rmax);

    // 5. top-10 + MLP
    final_kernel<<<NB, 256>>>(rmax, ff1w, ff1b, ff2w, ff2b, out);
}

// round 12
// speedup vs baseline: 3.0016x; 3.0016x over previous
#include <cuda_runtime.h>
#include <cuda_bf16.h>
#include <mma.h>
#include <math.h>
#include <stdint.h>

using namespace nvcuda;

#define DD 256
#define TWO_D 512
#define NB 16
#define AL 1024
#define TL 512

// ---------------- scratch (no allocations allowed) ----------------
__device__ float g_art0[NB * AL * DD];
__device__ float g_art1[NB * AL * DD];
__device__ float g_tpl0[NB * TL * DD];
__device__ float g_tpl1[NB * TL * DD];
__device__ __nv_bfloat16 g_axh0[NB * AL * DD];
__device__ __nv_bfloat16 g_axl0[NB * AL * DD];
__device__ __nv_bfloat16 g_axh1[NB * AL * DD];
__device__ __nv_bfloat16 g_axl1[NB * AL * DD];
__device__ __nv_bfloat16 g_txh0[NB * TL * DD];
__device__ __nv_bfloat16 g_txl0[NB * TL * DD];
__device__ __nv_bfloat16 g_txh1[NB * TL * DD];
__device__ __nv_bfloat16 g_txl1[NB * TL * DD];
__device__ __nv_bfloat16 g_wTh[10 * TWO_D * 768];   // [layer][co][k] K-contiguous
__device__ __nv_bfloat16 g_wTl[10 * TWO_D * 768];
__device__ __align__(16) __nv_bfloat16 g_zero16[8];  // zero-init
__device__ float g_a2[NB * AL];
__device__ float g_t2[NB * TL];
__device__ float g_rowmax[NB * AL];

__device__ __forceinline__ uint32_t smem_u32(const void* p) {
    uint32_t a;
    asm("{ .reg .u64 t; cvta.to.shared.u64 t, %1; cvt.u32.u64 %0, t; }" : "=r"(a) : "l"(p));
    return a;
}
__device__ __forceinline__ void cp16(uint32_t dst, const void* src) {
    asm volatile("cp.async.cg.shared.global [%0], [%1], 16;" :: "r"(dst), "l"(src));
}
#define CP_COMMIT() asm volatile("cp.async.commit_group;")

__device__ __forceinline__ __nv_bfloat16 bf_hi(float v) { return __float2bfloat16_rn(v); }
__device__ __forceinline__ __nv_bfloat16 bf_lo(float v, __nv_bfloat16 h) {
    return __float2bfloat16_rn(v - __bfloat162float(h));
}

// ---------------- weight transpose + hi/lo split: w[l][k][n] -> wT[l][n][k] ----------------
__global__ void wsplit_kernel(const float* __restrict__ exp_w, const float* __restrict__ ref_w,
                              __nv_bfloat16* __restrict__ wTh, __nv_bfloat16* __restrict__ wTl)
{
    __shared__ float t[32][33];
    const int l  = blockIdx.z;
    const float* src = (l < 7) ? exp_w + (size_t)l * 768 * TWO_D
                               : ref_w + (size_t)(l - 7) * 768 * TWO_D;
    const int k0 = blockIdx.x * 32, n0 = blockIdx.y * 32;
    for (int i = threadIdx.y; i < 32; i += 8)
        t[i][threadIdx.x] = src[(size_t)(k0 + i) * TWO_D + n0 + threadIdx.x];
    __syncthreads();
    for (int i = threadIdx.y; i < 32; i += 8) {
        float v = t[threadIdx.x][i];
        __nv_bfloat16 h = bf_hi(v);
        size_t o = (size_t)l * TWO_D * 768 + (size_t)(n0 + i) * 768 + k0 + threadIdx.x;
        wTh[o] = h;
        wTl[o] = bf_lo(v, h);
    }
}

// ---------------- embedding gather + hi/lo split ----------------
__global__ void gather_kernel(const int* __restrict__ idx, const float* __restrict__ emb,
                              float* __restrict__ out, __nv_bfloat16* __restrict__ oh,
                              __nv_bfloat16* __restrict__ ol, int nrows)
{
    int t = blockIdx.x * blockDim.x + threadIdx.x;
    int total = nrows * (DD / 4);
    if (t >= total) return;
    int row = t / (DD / 4);
    int c4  = t % (DD / 4);
    int w = idx[row];
    float4 v = reinterpret_cast<const float4*>(emb)[(size_t)w * (DD / 4) + c4];
    reinterpret_cast<float4*>(out)[(size_t)row * (DD / 4) + c4] = v;
    size_t eo = (size_t)row * DD + c4 * 4;
    __nv_bfloat16 hx = bf_hi(v.x), hy = bf_hi(v.y), hz = bf_hi(v.z), hw = bf_hi(v.w);
    *reinterpret_cast<__nv_bfloat162*>(oh + eo)     = __nv_bfloat162(hx, hy);
    *reinterpret_cast<__nv_bfloat162*>(oh + eo + 2) = __nv_bfloat162(hz, hw);
    *reinterpret_cast<__nv_bfloat162*>(ol + eo)     = __nv_bfloat162(bf_lo(v.x,hx), bf_lo(v.y,hy));
    *reinterpret_cast<__nv_bfloat162*>(ol + eo + 2) = __nv_bfloat162(bf_lo(v.z,hz), bf_lo(v.w,hw));
}

// ---------------- bf16x3 wmma conv1d(K=3,dil) + GLU + residual ----------------
// CTA: 128 pos x 128 cols (bc<64 -> a-col co0+bc ; bc>=64 -> g-col co0+192+bc).
#define BM 128
#define BK 32
#define AST 40                    // bf16 elems per tile row (32 + 8 pad)
#define SZT (128 * AST)           // elems per tile stage (A or B)
#define OFF_AH 0
#define OFF_AL (2 * SZT * 2)
#define OFF_BH (4 * SZT * 2)
#define OFF_BL (6 * SZT * 2)
#define C_STR 132
#define CONV_SMEM (8 * SZT * 2)   // 81920 B (> sC 67584)

__global__ __launch_bounds__(256, 2) void conv_tc_kernel(
    const float* __restrict__ x, const __nv_bfloat16* __restrict__ xh,
    const __nv_bfloat16* __restrict__ xl,
    float* __restrict__ out, __nv_bfloat16* __restrict__ oh, __nv_bfloat16* __restrict__ ol,
    const __nv_bfloat16* __restrict__ wTh, const __nv_bfloat16* __restrict__ wTl,
    const float* __restrict__ bias, int L, int dil)
{
    extern __shared__ __align__(16) char smraw[];
    const uint32_t sbase = smem_u32(smraw);
    float* sC = (float*)smraw;

    const int tid = threadIdx.x;
    const int wid = tid >> 5;
    const int l0  = blockIdx.x * BM;
    const int co0 = blockIdx.y * 64;
    const int b   = blockIdx.z;

    const float* xb = x + (size_t)b * L * DD;
    const __nv_bfloat16* xhb = xh + (size_t)b * L * DD;
    const __nv_bfloat16* xlb = xl + (size_t)b * L * DD;

    const int arow = tid >> 1;       // A/B staging row 0..127
    const int half = tid & 1;        // 16-elem half of the 32-elem row
    const int coln = (arow < 64) ? (co0 + arow) : (co0 + 192 + arow);
    const __nv_bfloat16* wThc = wTh + (size_t)coln * 768;
    const __nv_bfloat16* wTlc = wTl + (size_t)coln * 768;

    wmma::fragment<wmma::accumulator, 16, 16, 16, float> acc[2][4];
#pragma unroll
    for (int mi = 0; mi < 2; mi++)
#pragma unroll
        for (int ni = 0; ni < 4; ni++) wmma::fill_fragment(acc[mi][ni], 0.f);

    const int wm = (wid & 3) * 32;
    const int wn = (wid >> 2) * 64;

    auto issue_chunk = [&](int c, int sn) {
        const int tap = c >> 3;
        const int ci0 = (c & 7) * 32;
        const int k0  = c * 32;
        // A: activations hi/lo
        {
            const int p = l0 + arow + (tap - 1) * dil;
            const bool ok = (p >= 0 && p < L);
            const size_t go = (size_t)p * DD + ci0 + half * 16;
            const __nv_bfloat16* s0h = ok ? xhb + go : g_zero16;
            const __nv_bfloat16* s1h = ok ? s0h + 8  : g_zero16;
            const __nv_bfloat16* s0l = ok ? xlb + go : g_zero16;
            const __nv_bfloat16* s1l = ok ? s0l + 8  : g_zero16;
            const uint32_t doff = (uint32_t)(sn * SZT + arow * AST + half * 16) * 2;
            cp16(sbase + OFF_AH + doff,      s0h);
            cp16(sbase + OFF_AH + doff + 16, s1h);
            cp16(sbase + OFF_AL + doff,      s0l);
            cp16(sbase + OFF_AL + doff + 16, s1l);
        }
        // B: weights (transposed, K-contiguous) hi/lo
        {
            const __nv_bfloat16* sh = wThc + k0 + half * 16;
            const __nv_bfloat16* sl = wTlc + k0 + half * 16;
            const uint32_t doff = (uint32_t)(sn * SZT + arow * AST + half * 16) * 2;
            cp16(sbase + OFF_BH + doff,      sh);
            cp16(sbase + OFF_BH + doff + 16, sh + 8);
            cp16(sbase + OFF_BL + doff,      sl);
            cp16(sbase + OFF_BL + doff + 16, sl + 8);
        }
        CP_COMMIT();
    };

    issue_chunk(0, 0);

    for (int c = 0; c < 24; ++c) {
        const int st = c & 1;
        if (c < 23) issue_chunk(c + 1, st ^ 1);
        if (c < 23) asm volatile("cp.async.wait_group 1;" ::: "memory");
        else        asm volatile("cp.async.wait_group 0;" ::: "memory");
        __syncthreads();

        const __nv_bfloat16* pAh = (const __nv_bfloat16*)(smraw + OFF_AH) + st * SZT;
        const __nv_bfloat16* pAl = (const __nv_bfloat16*)(smraw + OFF_AL) + st * SZT;
        const __nv_bfloat16* pBh = (const __nv_bfloat16*)(smraw + OFF_BH) + st * SZT;
        const __nv_bfloat16* pBl = (const __nv_bfloat16*)(smraw + OFF_BL) + st * SZT;
#pragma unroll
        for (int ks = 0; ks < 2; ++ks) {
            wmma::fragment<wmma::matrix_a, 16, 16, 16, __nv_bfloat16, wmma::row_major> fah[2], fal[2];
#pragma unroll
            for (int mi = 0; mi < 2; mi++) {
                wmma::load_matrix_sync(fah[mi], pAh + (wm + mi * 16) * AST + ks * 16, AST);
                wmma::load_matrix_sync(fal[mi], pAl + (wm + mi * 16) * AST + ks * 16, AST);
            }
#pragma unroll
            for (int ni = 0; ni < 4; ni++) {
                wmma::fragment<wmma::matrix_b, 16, 16, 16, __nv_bfloat16, wmma::col_major> fbh, fbl;
                wmma::load_matrix_sync(fbh, pBh + (wn + ni * 16) * AST + ks * 16, AST);
                wmma::load_matrix_sync(fbl, pBl + (wn + ni * 16) * AST + ks * 16, AST);
#pragma unroll
                for (int mi = 0; mi < 2; mi++) {
                    wmma::mma_sync(acc[mi][ni], fah[mi], fbh, acc[mi][ni]);
                    wmma::mma_sync(acc[mi][ni], fah[mi], fbl, acc[mi][ni]);
                    wmma::mma_sync(acc[mi][ni], fal[mi], fbh, acc[mi][ni]);
                }
            }
        }
        __syncthreads();
    }

    // ---- accumulators -> smem ----
#pragma unroll
    for (int mi = 0; mi < 2; mi++)
#pragma unroll
        for (int ni = 0; ni < 4; ni++)
            wmma::store_matrix_sync(sC + (wm + mi * 16) * C_STR + wn + ni * 16,
                                    acc[mi][ni], C_STR, wmma::mem_row_major);
    __syncthreads();

    // ---- GLU epilogue: o = x + (a+ba)*sigmoid(g+bg); also write bf16 hi/lo ----
    {
        const int r  = tid >> 1;
        const int j0 = (tid & 1) * 32;
        const int l  = l0 + r;
        const float* xrow = xb + (size_t)l * DD + co0;
        const size_t obase = ((size_t)b * L + l) * DD + co0;
#pragma unroll
        for (int j = 0; j < 32; j += 4) {
            float4 xv = *reinterpret_cast<const float4*>(&xrow[j0 + j]);
            float o[4];
#pragma unroll
            for (int u = 0; u < 4; ++u) {
                int jj = j0 + j + u;
                float aa = sC[r * C_STR + jj] + bias[co0 + jj];
                float gg = sC[r * C_STR + 64 + jj] + bias[DD + co0 + jj];
                float xr = (u == 0) ? xv.x : (u == 1) ? xv.y : (u == 2) ? xv.z : xv.w;
                o[u] = xr + aa * (1.f / (1.f + expf(-gg)));
            }
            *reinterpret_cast<float4*>(out + obase + j0 + j) = make_float4(o[0], o[1], o[2], o[3]);
            __nv_bfloat16 h0 = bf_hi(o[0]), h1 = bf_hi(o[1]), h2 = bf_hi(o[2]), h3 = bf_hi(o[3]);
            *reinterpret_cast<__nv_bfloat162*>(oh + obase + j0 + j)     = __nv_bfloat162(h0, h1);
            *reinterpret_cast<__nv_bfloat162*>(oh + obase + j0 + j + 2) = __nv_bfloat162(h2, h3);
            *reinterpret_cast<__nv_bfloat162*>(ol + obase + j0 + j)     = __nv_bfloat162(bf_lo(o[0],h0), bf_lo(o[1],h1));
            *reinterpret_cast<__nv_bfloat162*>(ol + obase + j0 + j + 2) = __nv_bfloat162(bf_lo(o[2],h2), bf_lo(o[3],h3));
        }
    }
}

// ---------------- row squared norms ----------------
__global__ void norms_kernel(const float* __restrict__ x, float* __restrict__ out, int nrows)
{
    int warp = (blockIdx.x * blockDim.x + threadIdx.x) >> 5;
    int lane = threadIdx.x & 31;
    if (warp >= nrows) return;
    const float* r = x + (size_t)warp * DD;
    float s = 0.f;
#pragma unroll
    for (int c = lane * 2; c < DD; c += 64) {
        float2 v = *reinterpret_cast<const float2*>(&r[c]);
        s += v.x * v.x + v.y * v.y;
    }
#pragma unroll
    for (int o = 16; o; o >>= 1) s += __shfl_xor_sync(0xffffffffu, s, o);
    if (lane == 0) out[warp] = s;
}

// ---------------- fused distance GEMM + exp + mask + row-max ----------------
__global__ __launch_bounds__(256) void rowmax_kernel(
    const float* __restrict__ art, const float* __restrict__ tpl,
    const float* __restrict__ a2, const float* __restrict__ t2,
    const float* __restrict__ amask, const float* __restrict__ tmask,
    float* __restrict__ rowmax)
{
    __shared__ __align__(16) float As[16][68];
    __shared__ __align__(16) float Bs[16][68];

    const int l0  = blockIdx.x * 64;
    const int b   = blockIdx.y;
    const int tid = threadIdx.x;
    const int tx  = tid & 15;
    const int ty  = tid >> 4;

    const float* ab = art + (size_t)b * AL * DD;
    const float* tb = tpl + (size_t)b * TL * DD;

    const int am  = tid >> 2;
    const int akk = (tid & 3) * 4;

    float rmax[4] = {0.f, 0.f, 0.f, 0.f};

    for (int t0 = 0; t0 < TL; t0 += 64) {
        float acc[4][4];
#pragma unroll
        for (int i = 0; i < 4; i++)
#pragma unroll
            for (int j = 0; j < 4; j++) acc[i][j] = 0.f;

        for (int c = 0; c < 16; ++c) {
            int d0 = c * 16;
            float4 va = *reinterpret_cast<const float4*>(&ab[(size_t)(l0 + am) * DD + d0 + akk]);
            float4 vb = *reinterpret_cast<const float4*>(&tb[(size_t)(t0 + am) * DD + d0 + akk]);
            __syncthreads();
            As[akk + 0][am] = va.x; As[akk + 1][am] = va.y;
            As[akk + 2][am] = va.z; As[akk + 3][am] = va.w;
            Bs[akk + 0][am] = vb.x; Bs[akk + 1][am] = vb.y;
            Bs[akk + 2][am] = vb.z; Bs[akk + 3][am] = vb.w;
            __syncthreads();
#pragma unroll
            for (int kk = 0; kk < 16; ++kk) {
                float4 a4 = *reinterpret_cast<const float4*>(&As[kk][ty * 4]);
                float4 b4 = *reinterpret_cast<const float4*>(&Bs[kk][tx * 4]);
                float av[4] = {a4.x, a4.y, a4.z, a4.w};
                float bv[4] = {b4.x, b4.y, b4.z, b4.w};
#pragma unroll
                for (int i = 0; i < 4; i++)
#pragma unroll
                    for (int j = 0; j < 4; j++)
                        acc[i][j] = fmaf(av[i], bv[j], acc[i][j]);
            }
        }

#pragma unroll
        for (int i = 0; i < 4; i++) {
            int l = l0 + ty * 4 + i;
            float av2 = a2[b * AL + l];
#pragma unroll
            for (int j = 0; j < 4; j++) {
                int t = t0 + tx * 4 + j;
                float dist = av2 + t2[b * TL + t] - 2.f * acc[i][j];
                dist = fmaxf(dist, 0.f);
                float s = expf(-dist) * tmask[b * TL + t];
                rmax[i] = fmaxf(rmax[i], s);
            }
        }
    }

#pragma unroll
    for (int i = 0; i < 4; i++) {
        float v = rmax[i];
#pragma unroll
        for (int o = 8; o; o >>= 1) v = fmaxf(v, __shfl_xor_sync(0xffffffffu, v, o));
        if (tx == 0) {
            int l = l0 + ty * 4 + i;
            rowmax[b * AL + l] = v * amask[b * AL + l];
        }
    }
}

// ---------------- top-10 (sorted desc) + 2-layer MLP ----------------
__global__ void final_kernel(const float* __restrict__ rowmax,
                             const float* __restrict__ ff1w, const float* __restrict__ ff1b,
                             const float* __restrict__ ff2w, const float* __restrict__ ff2b,
                             float* __restrict__ out)
{
    __shared__ float vals[AL];
    __shared__ float rv[256];
    __shared__ int   ri[256];
    __shared__ float topv[10];

    int b = blockIdx.x;
    int tid = threadIdx.x;
    for (int i = tid; i < AL; i += 256) vals[i] = rowmax[b * AL + i];
    __syncthreads();

    for (int it = 0; it < 10; ++it) {
        float bv = -1.f; int bi = 0;
        for (int i = tid; i < AL; i += 256) {
            float v = vals[i];
            if (v > bv) { bv = v; bi = i; }
        }
        rv[tid] = bv; ri[tid] = bi;
        __syncthreads();
        for (int s = 128; s; s >>= 1) {
            if (tid < s && rv[tid + s] > rv[tid]) { rv[tid] = rv[tid + s]; ri[tid] = ri[tid + s]; }
            __syncthreads();
        }
        if (tid == 0) { topv[it] = rv[0]; vals[ri[0]] = -2.f; }
        __syncthreads();
    }

    if (tid == 0) {
        float o = ff2b[0];
#pragma unroll
        for (int j = 0; j < 10; j++) {
            float h = ff1b[j];
#pragma unroll
            for (int i = 0; i < 10; i++) h += topv[i] * ff1w[i * 10 + j];
            h = fmaxf(h, 0.f);
            o += h * ff2w[j];
        }
        out[b] = o;
    }
}

// ---------------- launcher ----------------
extern "C" void kernel_launch(void* const* d_in, const int* in_sizes, int n_in,
                              void* d_out, int out_size)
{
    const int*   art_w = (const int*)d_in[0];
    const int*   tpl_w = (const int*)d_in[2];
    const float* amask = (const float*)d_in[4];
    const float* tmask = (const float*)d_in[5];
    const float* emb   = (const float*)d_in[6];
    const float* exp_w = (const float*)d_in[7];
    const float* exp_b = (const float*)d_in[8];
    const float* ref_w = (const float*)d_in[9];
    const float* ref_b = (const float*)d_in[10];
    const float* ff1w  = (const float*)d_in[11];
    const float* ff1b  = (const float*)d_in[12];
    const float* ff2w  = (const float*)d_in[13];
    const float* ff2b  = (const float*)d_in[14];
    float* out = (float*)d_out;

    float *art0, *art1, *tpl0, *tpl1, *a2, *t2, *rmax;
    __nv_bfloat16 *axh0, *axl0, *axh1, *axl1, *txh0, *txl0, *txh1, *txl1, *wTh, *wTl;
    cudaGetSymbolAddress((void**)&art0, g_art0);
    cudaGetSymbolAddress((void**)&art1, g_art1);
    cudaGetSymbolAddress((void**)&tpl0, g_tpl0);
    cudaGetSymbolAddress((void**)&tpl1, g_tpl1);
    cudaGetSymbolAddress((void**)&axh0, g_axh0);
    cudaGetSymbolAddress((void**)&axl0, g_axl0);
    cudaGetSymbolAddress((void**)&axh1, g_axh1);
    cudaGetSymbolAddress((void**)&axl1, g_axl1);
    cudaGetSymbolAddress((void**)&txh0, g_txh0);
    cudaGetSymbolAddress((void**)&txl0, g_txl0);
    cudaGetSymbolAddress((void**)&txh1, g_txh1);
    cudaGetSymbolAddress((void**)&txl1, g_txl1);
    cudaGetSymbolAddress((void**)&wTh,  g_wTh);
    cudaGetSymbolAddress((void**)&wTl,  g_wTl);
    cudaGetSymbolAddress((void**)&a2,   g_a2);
    cudaGetSymbolAddress((void**)&t2,   g_t2);
    cudaGetSymbolAddress((void**)&rmax, g_rowmax);

    cudaFuncSetAttribute(conv_tc_kernel,
                         cudaFuncAttributeMaxDynamicSharedMemorySize, CONV_SMEM);

    // 0. weights: transpose + bf16 hi/lo split (per-launch, ~50us)
    wsplit_kernel<<<dim3(24, 16, 10), dim3(32, 8)>>>(exp_w, ref_w, wTh, wTl);

    // 1. embedding gathers (+ split)
    gather_kernel<<<(NB * AL * (DD / 4) + 255) / 256, 256>>>(art_w, emb, art0, axh0, axl0, NB * AL);
    gather_kernel<<<(NB * TL * (DD / 4) + 255) / 256, 256>>>(tpl_w, emb, tpl0, txh0, txl0, NB * TL);

    // 2. 10 residual conv-GLU blocks (bf16x3 wmma + cp.async)
    const int dils[10] = {1, 2, 4, 8, 16, 32, 32, 1, 1, 1};
    for (int i = 0; i < 10; ++i) {
        const __nv_bfloat16* wh = wTh + (size_t)i * TWO_D * 768;
        const __nv_bfloat16* wl = wTl + (size_t)i * TWO_D * 768;
        const float* bb = (i < 7) ? exp_b + i * TWO_D : ref_b + (i - 7) * TWO_D;
        float *ain  = (i & 1) ? art1 : art0, *aout = (i & 1) ? art0 : art1;
        float *tin  = (i & 1) ? tpl1 : tpl0, *tout = (i & 1) ? tpl0 : tpl1;
        __nv_bfloat16 *aih = (i & 1) ? axh1 : axh0, *ail = (i & 1) ? axl1 : axl0;
        __nv_bfloat16 *aoh = (i & 1) ? axh0 : axh1, *aol = (i & 1) ? axl0 : axl1;
        __nv_bfloat16 *tih = (i & 1) ? txh1 : txh0, *til = (i & 1) ? txl1 : txl0;
        __nv_bfloat16 *toh = (i & 1) ? txh0 : txh1, *tol = (i & 1) ? txl0 : txl1;
        conv_tc_kernel<<<dim3(AL / BM, 4, NB), 256, CONV_SMEM>>>(
            ain, aih, ail, aout, aoh, aol, wh, wl, bb, AL, dils[i]);
        conv_tc_kernel<<<dim3(TL / BM, 4, NB), 256, CONV_SMEM>>>(
            tin, tih, til, tout, toh, tol, wh, wl, bb, TL, dils[i]);
    }

    // 3. squared norms
    norms_kernel<<<(NB * AL) / 8, 256>>>(art0, a2, NB * AL);
    norms_kernel<<<(NB * TL) / 8, 256>>>(tpl0, t2, NB * TL);

    // 4. fused distance + exp + mask + row-max
    rowmax_kernel<<<dim3(AL / 64, NB), 256>>>(art0, tpl0, a2, t2, amask, tmask, rmax);

    // 5. top-10 + MLP
    final_kernel<<<NB, 256>>>(rmax, ff1w, ff1b, ff2w, ff2b, out);
}